// round 11
// baseline (speedup 1.0000x reference)
#include <cuda_runtime.h>
#include <cuda_fp16.h>
#include <math.h>
#include <stdint.h>

// ConvEncoder: y = GELU(im2col(emb[x]) @ W^T + b).  M=32768, N=128, K=640.
// R11: single-pass fp16 (R10 math, rel_err 3.1e-4) with 2 CTAs/SM:
// TOK=128, 256 threads, 256 CTAs. One CTA's gather/GELU overlaps the
// co-resident CTA's tensor mainloop. W: 2-slot ring of K=128 chunks.

#define CE_S    2048
#define CE_KTOT 640
#define THREADS 256
#define TOK     128
#define ROW_B   272                  // fp16 row: 256B data + 16B pad (A and W)

// smem layout (bytes)
#define SA      0                    // 132 rows * 272 = 35904
#define SW_BASE 35904                // 2 slots x 34816 (128 rows * 272)
#define SW_SLOT 34816
#define SBIAS   105536
#define SIDX    106048               // 132 ints
#define SM_TOT  106624

// W pre-converted fp16: [kc(5)][o(128)][272B]
__device__ __align__(16) unsigned char g_Wcvt[5 * 128 * ROW_B];

__device__ __forceinline__ float gelu_exact(float y) {
    return 0.5f * y * (1.0f + erff(y * 0.70710678118654752f));
}

__device__ __forceinline__ void mma_f16(float* c, const uint32_t* a, const uint32_t* b) {
    asm volatile(
        "mma.sync.aligned.m16n8k16.row.col.f32.f16.f16.f32 "
        "{%0,%1,%2,%3}, {%4,%5,%6,%7}, {%8,%9}, {%0,%1,%2,%3};"
        : "+f"(c[0]), "+f"(c[1]), "+f"(c[2]), "+f"(c[3])
        : "r"(a[0]), "r"(a[1]), "r"(a[2]), "r"(a[3]), "r"(b[0]), "r"(b[1]));
}

__device__ __forceinline__ void ldsm4(uint32_t* r, uint32_t addr) {
    asm volatile("ldmatrix.sync.aligned.m8n8.x4.shared.b16 {%0,%1,%2,%3}, [%4];"
                 : "=r"(r[0]), "=r"(r[1]), "=r"(r[2]), "=r"(r[3]) : "r"(addr));
}

__device__ __forceinline__ void cpasync16(uint32_t dst, const void* src) {
    asm volatile("cp.async.cg.shared.global [%0], [%1], 16;"
                 :: "r"(dst), "l"(src) : "memory");
}

// convert 8 f32 -> 8 fp16 packed as uint4 (16 bytes)
__device__ __forceinline__ uint4 cvt8_f16(float4 v0, float4 v1) {
    union { __half2 h[4]; uint4 u; } p;
    p.h[0] = __float22half2_rn(make_float2(v0.x, v0.y));
    p.h[1] = __float22half2_rn(make_float2(v0.z, v0.w));
    p.h[2] = __float22half2_rn(make_float2(v1.x, v1.y));
    p.h[3] = __float22half2_rn(make_float2(v1.z, v1.w));
    return p.u;
}

// ---- prep: W f32 -> fp16, chunked layout for direct cp.async ----
__global__ void __launch_bounds__(256)
prep_w_kernel(const float* __restrict__ W)
{
    int t = blockIdx.x * 256 + threadIdx.x;        // 5*128*16 = 10240 granules
    if (t >= 5 * 128 * 16) return;
    int gnl = t & 15;
    int o   = (t >> 4) & 127;
    int kc  = t >> 11;
    const float* src = W + (size_t)o * CE_KTOT + kc * 128 + gnl * 8;
    float4 v0 = *reinterpret_cast<const float4*>(src);
    float4 v1 = *reinterpret_cast<const float4*>(src + 4);
    *reinterpret_cast<uint4*>(g_Wcvt + ((size_t)kc * 128 + o) * ROW_B + gnl * 16)
        = cvt8_f16(v0, v1);
}

// stage one K=128 W chunk into a smem ring slot via cp.async
__device__ __forceinline__ void stage_w(uint32_t swdst, int kc, int tid) {
    const unsigned char* base = g_Wcvt + (size_t)kc * 128 * ROW_B;
    #pragma unroll
    for (int it = 0; it < 8; ++it) {
        int idx = tid + it * THREADS;              // 2048: 128 o x 16 granules
        int o = idx >> 4, gnl = idx & 15;
        cpasync16(swdst + o * ROW_B + gnl * 16,
                  base + (size_t)o * ROW_B + gnl * 16);
    }
}

__global__ void __launch_bounds__(THREADS, 2)
conv_encoder_hmma(const int* __restrict__ x,
                  const float* __restrict__ emb,
                  const float* __restrict__ bias,
                  float* __restrict__ out)
{
    extern __shared__ uint8_t smem[];
    uint32_t sb;
    asm("{ .reg .u64 t; cvta.to.shared.u64 t, %1; cvt.u32.u64 %0, t; }"
        : "=r"(sb) : "l"(smem));

    const int tid = threadIdx.x;
    const int wid = tid >> 5;
    const int lid = tid & 31;
    const int g   = lid >> 2;
    const int q   = lid & 3;
    const int wm  = wid >> 2;       // 0..1  (64-row band within 128)
    const int wn  = wid & 3;        // 0..3  (32-col band)
    const int batch = blockIdx.y;
    const int s0 = blockIdx.x * TOK;

    // prefetch W chunks 0 and 1 (overlaps the A gather)
    stage_w(sb + SW_BASE, 0, tid);
    asm volatile("cp.async.commit_group;" ::: "memory");
    stage_w(sb + SW_BASE + SW_SLOT, 1, tid);
    asm volatile("cp.async.commit_group;" ::: "memory");

    if (tid < 32) {
        reinterpret_cast<float4*>(smem + SBIAS)[tid] =
            reinterpret_cast<const float4*>(bias)[tid];
    }
    // token index cache: halo rows p=0..131 -> seq s0+p-2 (or -1 if OOB)
    if (tid >= THREADS - 132) {
        int p = tid - (THREADS - 132);
        int s = s0 + p - 2;
        reinterpret_cast<int*>(smem + SIDX)[p] =
            (s >= 0 && s < CE_S) ? x[batch * CE_S + s] : -1;
    }
    __syncthreads();

    // ---- stage halo'd A once: rows p=0..131, fp16 ----
    #pragma unroll
    for (int it = 0; it < 9; ++it) {
        int idx = tid + it * THREADS;              // 132*16 = 2112 tasks (32B each)
        if (idx < 132 * 16) {
            int p = idx >> 4;
            int c = idx & 15;                      // 16B fp16 granule = 8 elems
            int tok = reinterpret_cast<const int*>(smem + SIDX)[p];
            float4 v0 = make_float4(0.f, 0.f, 0.f, 0.f);
            float4 v1 = v0;
            if (tok >= 0) {
                const float* e = emb + (size_t)tok * 128 + c * 8;
                v0 = *reinterpret_cast<const float4*>(e);
                v1 = *reinterpret_cast<const float4*>(e + 4);
            }
            *reinterpret_cast<uint4*>(smem + SA + p * ROW_B + c * 16) = cvt8_f16(v0, v1);
        }
    }

    float acc[4][4][4];
    #pragma unroll
    for (int i = 0; i < 4; ++i)
        #pragma unroll
        for (int j = 0; j < 4; ++j)
            #pragma unroll
            for (int r = 0; r < 4; ++r)
                acc[i][j][r] = 0.f;

    // per-lane ldmatrix offsets
    const uint32_t a_off = ((lid & 7) + ((lid >> 3) & 1) * 8) * ROW_B + (lid >> 4) * 16;
    // B (x4, j-paired): lanes 0-15 -> n-tile j (k halves), 16-31 -> n-tile j+1
    const uint32_t b_off = ((lid & 7) + (lid >> 4) * 8) * ROW_B + ((lid >> 3) & 1) * 16;

    // ---- 5 chunks of K=128, 2-slot ring ----
    for (int s = 0; s < 5; ++s) {
        if (s < 4) {
            asm volatile("cp.async.wait_group 1;" ::: "memory");
        } else {
            asm volatile("cp.async.wait_group 0;" ::: "memory");
        }
        __syncthreads();

        const uint32_t swb = sb + SW_BASE + (s & 1) * SW_SLOT;
        const uint32_t aA  = sb + SA + (wm * 64 + s) * ROW_B + a_off;
        const uint32_t aB  = swb + wn * 32 * ROW_B + b_off;

        #pragma unroll
        for (int ks = 0; ks < 8; ++ks) {
            const uint32_t kb = ks * 32;
            uint32_t Ah[4][4], Bp[2][4];
            #pragma unroll
            for (int i = 0; i < 4; ++i)
                ldsm4(Ah[i], aA + i * (16 * ROW_B) + kb);
            #pragma unroll
            for (int jp = 0; jp < 2; ++jp)
                ldsm4(Bp[jp], aB + jp * (16 * ROW_B) + kb);
            #pragma unroll
            for (int i = 0; i < 4; ++i)
                #pragma unroll
                for (int j = 0; j < 4; ++j)
                    mma_f16(acc[i][j], Ah[i], &Bp[j >> 1][(j & 1) * 2]);
        }

        __syncthreads();   // readers done before ring slot reuse
        if (s < 3) {
            stage_w(sb + SW_BASE + (s & 1) * SW_SLOT, s + 2, tid);
            asm volatile("cp.async.commit_group;" ::: "memory");
        }
    }

    // ---- epilogue: bias + exact GELU + store ----
    const float* bs = reinterpret_cast<const float*>(smem + SBIAS);
    #pragma unroll
    for (int i = 0; i < 4; ++i) {
        int row0 = s0 + wm * 64 + i * 16 + g;
        #pragma unroll
        for (int j = 0; j < 4; ++j) {
            int col = wn * 32 + j * 8 + q * 2;
            float b0 = bs[col], b1 = bs[col + 1];
            float2 v0, v1;
            v0.x = gelu_exact(acc[i][j][0] + b0);
            v0.y = gelu_exact(acc[i][j][1] + b1);
            v1.x = gelu_exact(acc[i][j][2] + b0);
            v1.y = gelu_exact(acc[i][j][3] + b1);
            float* p0 = out + ((size_t)(batch * CE_S + row0)) * 128 + col;
            *reinterpret_cast<float2*>(p0) = v0;
            *reinterpret_cast<float2*>(p0 + 8 * 128) = v1;
        }
    }
}

extern "C" void kernel_launch(void* const* d_in, const int* in_sizes, int n_in,
                              void* d_out, int out_size)
{
    const int*   x    = (const int*)  d_in[0];
    const float* emb  = (const float*)d_in[1];
    const float* W    = (const float*)d_in[2];
    const float* bias = (const float*)d_in[3];
    float*       out  = (float*)d_out;

    prep_w_kernel<<<40, 256>>>(W);

    cudaFuncSetAttribute(conv_encoder_hmma,
                         cudaFuncAttributeMaxDynamicSharedMemorySize, SM_TOT);
    dim3 grid(CE_S / TOK, 16);   // 16 x 16 = 256 CTAs, 2 per SM
    conv_encoder_hmma<<<grid, THREADS, SM_TOT>>>(x, emb, bias, out);
}

// round 12
// speedup vs baseline: 1.6460x; 1.6460x over previous
#include <cuda_runtime.h>
#include <cuda_fp16.h>
#include <math.h>
#include <stdint.h>

// ConvEncoder: y = GELU(im2col(emb[x]) @ W^T + b).  M=32768, N=128, K=640.
// R12: R10 base (single-pass fp16, TOK=256, 512 thr, 128 CTAs = 1 wave)
// + GELU via HW tanh.approx.f32 (epilogue ~2.5x cheaper, adds ~1.5e-4 err)
// + 3-slot W ring with ONE __syncthreads per chunk; next chunk's cp.async
//   issued before the MMAs so it overlaps them.

#define CE_S    2048
#define CE_KTOT 640
#define THREADS 512
#define TOK     256
#define ROW_B   272                  // fp16 row: 256B data + 16B pad (A and W)

// smem layout (bytes)
#define SA      0                    // 260 rows * 272
#define SW_BASE 70720                // 3 slots x 34816 (128 rows * 272)
#define SW_SLOT 34816
#define SBIAS   175168
#define SIDX    175680               // 260 ints
#define SM_TOT  176768

// W pre-converted fp16: [kc(5)][o(128)][272B]
__device__ __align__(16) unsigned char g_Wcvt[5 * 128 * ROW_B];

// GELU, tanh form with HW MUFU tanh:
// 0.5x(1+tanh(0.79788456(x+0.044715x^3))) = 0.5x(1+tanh(x*(c0+c1*x^2)))
__device__ __forceinline__ float gelu_fast(float x) {
    float t = x * fmaf(0.03567740814f, x * x, 0.79788456080f);
    float th;
    asm("tanh.approx.f32 %0, %1;" : "=f"(th) : "f"(t));
    float h = 0.5f * x;
    return fmaf(h, th, h);
}

__device__ __forceinline__ void mma_f16(float* c, const uint32_t* a, const uint32_t* b) {
    asm volatile(
        "mma.sync.aligned.m16n8k16.row.col.f32.f16.f16.f32 "
        "{%0,%1,%2,%3}, {%4,%5,%6,%7}, {%8,%9}, {%0,%1,%2,%3};"
        : "+f"(c[0]), "+f"(c[1]), "+f"(c[2]), "+f"(c[3])
        : "r"(a[0]), "r"(a[1]), "r"(a[2]), "r"(a[3]), "r"(b[0]), "r"(b[1]));
}

__device__ __forceinline__ void ldsm4(uint32_t* r, uint32_t addr) {
    asm volatile("ldmatrix.sync.aligned.m8n8.x4.shared.b16 {%0,%1,%2,%3}, [%4];"
                 : "=r"(r[0]), "=r"(r[1]), "=r"(r[2]), "=r"(r[3]) : "r"(addr));
}

__device__ __forceinline__ void cpasync16(uint32_t dst, const void* src) {
    asm volatile("cp.async.cg.shared.global [%0], [%1], 16;"
                 :: "r"(dst), "l"(src) : "memory");
}

// convert 8 f32 -> 8 fp16 packed as uint4 (16 bytes)
__device__ __forceinline__ uint4 cvt8_f16(float4 v0, float4 v1) {
    union { __half2 h[4]; uint4 u; } p;
    p.h[0] = __float22half2_rn(make_float2(v0.x, v0.y));
    p.h[1] = __float22half2_rn(make_float2(v0.z, v0.w));
    p.h[2] = __float22half2_rn(make_float2(v1.x, v1.y));
    p.h[3] = __float22half2_rn(make_float2(v1.z, v1.w));
    return p.u;
}

// ---- prep: W f32 -> fp16, chunked layout for direct cp.async ----
__global__ void __launch_bounds__(256)
prep_w_kernel(const float* __restrict__ W)
{
    int t = blockIdx.x * 256 + threadIdx.x;        // 5*128*16 = 10240 granules
    if (t >= 5 * 128 * 16) return;
    int gnl = t & 15;
    int o   = (t >> 4) & 127;
    int kc  = t >> 11;
    const float* src = W + (size_t)o * CE_KTOT + kc * 128 + gnl * 8;
    float4 v0 = *reinterpret_cast<const float4*>(src);
    float4 v1 = *reinterpret_cast<const float4*>(src + 4);
    *reinterpret_cast<uint4*>(g_Wcvt + ((size_t)kc * 128 + o) * ROW_B + gnl * 16)
        = cvt8_f16(v0, v1);
}

// stage one K=128 W chunk into a smem ring slot via cp.async
__device__ __forceinline__ void stage_w(uint32_t swdst, int kc, int tid) {
    const unsigned char* base = g_Wcvt + (size_t)kc * 128 * ROW_B;
    #pragma unroll
    for (int it = 0; it < 4; ++it) {
        int idx = tid + it * THREADS;              // 2048: 128 o x 16 granules
        int o = idx >> 4, gnl = idx & 15;
        cpasync16(swdst + o * ROW_B + gnl * 16,
                  base + (size_t)o * ROW_B + gnl * 16);
    }
}

__global__ void __launch_bounds__(THREADS, 1)
conv_encoder_hmma(const int* __restrict__ x,
                  const float* __restrict__ emb,
                  const float* __restrict__ bias,
                  float* __restrict__ out)
{
    extern __shared__ uint8_t smem[];
    uint32_t sb;
    asm("{ .reg .u64 t; cvta.to.shared.u64 t, %1; cvt.u32.u64 %0, t; }"
        : "=r"(sb) : "l"(smem));

    const int tid = threadIdx.x;
    const int wid = tid >> 5;
    const int lid = tid & 31;
    const int g   = lid >> 2;
    const int q   = lid & 3;
    const int wm  = wid >> 2;       // 0..3  (64-row band within 256)
    const int wn  = wid & 3;        // 0..3  (32-col band)
    const int batch = blockIdx.y;
    const int s0 = blockIdx.x * TOK;

    // prefetch W chunks 0 and 1 (overlaps the A gather)
    stage_w(sb + SW_BASE, 0, tid);
    asm volatile("cp.async.commit_group;" ::: "memory");
    stage_w(sb + SW_BASE + SW_SLOT, 1, tid);
    asm volatile("cp.async.commit_group;" ::: "memory");

    if (tid < 32) {
        reinterpret_cast<float4*>(smem + SBIAS)[tid] =
            reinterpret_cast<const float4*>(bias)[tid];
    }
    // token index cache: halo rows p=0..259 -> seq s0+p-2 (or -1 if OOB)
    if (tid >= THREADS - 260) {
        int p = tid - (THREADS - 260);
        int s = s0 + p - 2;
        reinterpret_cast<int*>(smem + SIDX)[p] =
            (s >= 0 && s < CE_S) ? x[batch * CE_S + s] : -1;
    }
    __syncthreads();

    // ---- stage halo'd A once: rows p=0..259, fp16 ----
    #pragma unroll
    for (int it = 0; it < 9; ++it) {
        int idx = tid + it * THREADS;              // 260*16 = 4160 tasks (32B each)
        if (idx < 260 * 16) {
            int p = idx >> 4;
            int c = idx & 15;                      // 16B fp16 granule = 8 elems
            int tok = reinterpret_cast<const int*>(smem + SIDX)[p];
            float4 v0 = make_float4(0.f, 0.f, 0.f, 0.f);
            float4 v1 = v0;
            if (tok >= 0) {
                const float* e = emb + (size_t)tok * 128 + c * 8;
                v0 = *reinterpret_cast<const float4*>(e);
                v1 = *reinterpret_cast<const float4*>(e + 4);
            }
            *reinterpret_cast<uint4*>(smem + SA + p * ROW_B + c * 16) = cvt8_f16(v0, v1);
        }
    }

    float acc[4][4][4];
    #pragma unroll
    for (int i = 0; i < 4; ++i)
        #pragma unroll
        for (int j = 0; j < 4; ++j)
            #pragma unroll
            for (int r = 0; r < 4; ++r)
                acc[i][j][r] = 0.f;

    // per-lane ldmatrix offsets
    const uint32_t a_off = ((lid & 7) + ((lid >> 3) & 1) * 8) * ROW_B + (lid >> 4) * 16;
    // B (x4, j-paired): lanes 0-15 -> n-tile j (k halves), 16-31 -> n-tile j+1
    const uint32_t b_off = ((lid & 7) + (lid >> 4) * 8) * ROW_B + ((lid >> 3) & 1) * 16;

    // ---- 5 chunks of K=128, 3-slot ring, ONE sync per chunk ----
    // iter s: wait own groups for chunk s -> sync (visibility of all threads'
    // portions + release slot (s+2)%3) -> stage chunk s+2 (overlaps MMAs).
    #pragma unroll
    for (int s = 0; s < 5; ++s) {
        if (s < 4) {
            asm volatile("cp.async.wait_group 1;" ::: "memory");
        } else {
            asm volatile("cp.async.wait_group 0;" ::: "memory");
        }
        __syncthreads();
        if (s < 3) {
            stage_w(sb + SW_BASE + ((s + 2) % 3) * SW_SLOT, s + 2, tid);
            asm volatile("cp.async.commit_group;" ::: "memory");
        }

        const uint32_t swb = sb + SW_BASE + (s % 3) * SW_SLOT;
        const uint32_t aA  = sb + SA + (wm * 64 + s) * ROW_B + a_off;
        const uint32_t aB  = swb + wn * 32 * ROW_B + b_off;

        #pragma unroll
        for (int ks = 0; ks < 8; ++ks) {
            const uint32_t kb = ks * 32;
            uint32_t Ah[4][4], Bp[2][4];
            #pragma unroll
            for (int i = 0; i < 4; ++i)
                ldsm4(Ah[i], aA + i * (16 * ROW_B) + kb);
            #pragma unroll
            for (int jp = 0; jp < 2; ++jp)
                ldsm4(Bp[jp], aB + jp * (16 * ROW_B) + kb);
            #pragma unroll
            for (int i = 0; i < 4; ++i)
                #pragma unroll
                for (int j = 0; j < 4; ++j)
                    mma_f16(acc[i][j], Ah[i], &Bp[j >> 1][(j & 1) * 2]);
        }
    }

    // ---- epilogue: bias + fast GELU + store ----
    const float* bs = reinterpret_cast<const float*>(smem + SBIAS);
    #pragma unroll
    for (int i = 0; i < 4; ++i) {
        int row0 = s0 + wm * 64 + i * 16 + g;
        #pragma unroll
        for (int j = 0; j < 4; ++j) {
            int col = wn * 32 + j * 8 + q * 2;
            float b0 = bs[col], b1 = bs[col + 1];
            float2 v0, v1;
            v0.x = gelu_fast(acc[i][j][0] + b0);
            v0.y = gelu_fast(acc[i][j][1] + b1);
            v1.x = gelu_fast(acc[i][j][2] + b0);
            v1.y = gelu_fast(acc[i][j][3] + b1);
            float* p0 = out + ((size_t)(batch * CE_S + row0)) * 128 + col;
            *reinterpret_cast<float2*>(p0) = v0;
            *reinterpret_cast<float2*>(p0 + 8 * 128) = v1;
        }
    }
}

extern "C" void kernel_launch(void* const* d_in, const int* in_sizes, int n_in,
                              void* d_out, int out_size)
{
    const int*   x    = (const int*)  d_in[0];
    const float* emb  = (const float*)d_in[1];
    const float* W    = (const float*)d_in[2];
    const float* bias = (const float*)d_in[3];
    float*       out  = (float*)d_out;

    prep_w_kernel<<<40, 256>>>(W);

    cudaFuncSetAttribute(conv_encoder_hmma,
                         cudaFuncAttributeMaxDynamicSharedMemorySize, SM_TOT);
    dim3 grid(CE_S / TOK, 16);   // 8 x 16 = 128 CTAs (one wave)
    conv_encoder_hmma<<<grid, THREADS, SM_TOT>>>(x, emb, bias, out);
}

// round 13
// speedup vs baseline: 1.6607x; 1.0089x over previous
#include <cuda_runtime.h>
#include <cuda_fp16.h>
#include <math.h>
#include <stdint.h>

// ConvEncoder: y = GELU(im2col(emb[x]) @ W^T + b).  M=32768, N=128, K=640.
// R13: R12 math (single-pass fp16, tanh GELU, 3-slot W ring) with 8 warps
// of 64x64 tiles (4m x 2n) instead of 16 warps of 64x32: smem LDSM traffic
// drops 33% (1.92MB -> 1.28MB per CTA). 256 thr, TOK=256, 128 CTAs = 1 wave.

#define CE_S    2048
#define CE_KTOT 640
#define THREADS 256
#define TOK     256
#define ROW_B   272                  // fp16 row: 256B data + 16B pad (A and W)

// smem layout (bytes)
#define SA      0                    // 260 rows * 272
#define SW_BASE 70720                // 3 slots x 34816 (128 rows * 272)
#define SW_SLOT 34816
#define SBIAS   175168
#define SIDX    175680               // 260 ints
#define SM_TOT  176768

// W pre-converted fp16: [kc(5)][o(128)][272B]
__device__ __align__(16) unsigned char g_Wcvt[5 * 128 * ROW_B];

// GELU, tanh form with HW MUFU tanh
__device__ __forceinline__ float gelu_fast(float x) {
    float t = x * fmaf(0.03567740814f, x * x, 0.79788456080f);
    float th;
    asm("tanh.approx.f32 %0, %1;" : "=f"(th) : "f"(t));
    float h = 0.5f * x;
    return fmaf(h, th, h);
}

__device__ __forceinline__ void mma_f16(float* c, const uint32_t* a, const uint32_t* b) {
    asm volatile(
        "mma.sync.aligned.m16n8k16.row.col.f32.f16.f16.f32 "
        "{%0,%1,%2,%3}, {%4,%5,%6,%7}, {%8,%9}, {%0,%1,%2,%3};"
        : "+f"(c[0]), "+f"(c[1]), "+f"(c[2]), "+f"(c[3])
        : "r"(a[0]), "r"(a[1]), "r"(a[2]), "r"(a[3]), "r"(b[0]), "r"(b[1]));
}

__device__ __forceinline__ void ldsm4(uint32_t* r, uint32_t addr) {
    asm volatile("ldmatrix.sync.aligned.m8n8.x4.shared.b16 {%0,%1,%2,%3}, [%4];"
                 : "=r"(r[0]), "=r"(r[1]), "=r"(r[2]), "=r"(r[3]) : "r"(addr));
}

__device__ __forceinline__ void cpasync16(uint32_t dst, const void* src) {
    asm volatile("cp.async.cg.shared.global [%0], [%1], 16;"
                 :: "r"(dst), "l"(src) : "memory");
}

// convert 8 f32 -> 8 fp16 packed as uint4 (16 bytes)
__device__ __forceinline__ uint4 cvt8_f16(float4 v0, float4 v1) {
    union { __half2 h[4]; uint4 u; } p;
    p.h[0] = __float22half2_rn(make_float2(v0.x, v0.y));
    p.h[1] = __float22half2_rn(make_float2(v0.z, v0.w));
    p.h[2] = __float22half2_rn(make_float2(v1.x, v1.y));
    p.h[3] = __float22half2_rn(make_float2(v1.z, v1.w));
    return p.u;
}

// ---- prep: W f32 -> fp16, chunked layout for direct cp.async ----
__global__ void __launch_bounds__(256)
prep_w_kernel(const float* __restrict__ W)
{
    int t = blockIdx.x * 256 + threadIdx.x;        // 5*128*16 = 10240 granules
    if (t >= 5 * 128 * 16) return;
    int gnl = t & 15;
    int o   = (t >> 4) & 127;
    int kc  = t >> 11;
    const float* src = W + (size_t)o * CE_KTOT + kc * 128 + gnl * 8;
    float4 v0 = *reinterpret_cast<const float4*>(src);
    float4 v1 = *reinterpret_cast<const float4*>(src + 4);
    *reinterpret_cast<uint4*>(g_Wcvt + ((size_t)kc * 128 + o) * ROW_B + gnl * 16)
        = cvt8_f16(v0, v1);
}

// stage one K=128 W chunk into a smem ring slot via cp.async
__device__ __forceinline__ void stage_w(uint32_t swdst, int kc, int tid) {
    const unsigned char* base = g_Wcvt + (size_t)kc * 128 * ROW_B;
    #pragma unroll
    for (int it = 0; it < 8; ++it) {
        int idx = tid + it * THREADS;              // 2048: 128 o x 16 granules
        int o = idx >> 4, gnl = idx & 15;
        cpasync16(swdst + o * ROW_B + gnl * 16,
                  base + (size_t)o * ROW_B + gnl * 16);
    }
}

__global__ void __launch_bounds__(THREADS)
conv_encoder_hmma(const int* __restrict__ x,
                  const float* __restrict__ emb,
                  const float* __restrict__ bias,
                  float* __restrict__ out)
{
    extern __shared__ uint8_t smem[];
    uint32_t sb;
    asm("{ .reg .u64 t; cvta.to.shared.u64 t, %1; cvt.u32.u64 %0, t; }"
        : "=r"(sb) : "l"(smem));

    const int tid = threadIdx.x;
    const int wid = tid >> 5;
    const int lid = tid & 31;
    const int g   = lid >> 2;
    const int q   = lid & 3;
    const int wm  = wid >> 1;       // 0..3  (64-row band within 256)
    const int wn  = wid & 1;        // 0..1  (64-col band)
    const int batch = blockIdx.y;
    const int s0 = blockIdx.x * TOK;

    // prefetch W chunks 0 and 1 (overlaps the A gather)
    stage_w(sb + SW_BASE, 0, tid);
    asm volatile("cp.async.commit_group;" ::: "memory");
    stage_w(sb + SW_BASE + SW_SLOT, 1, tid);
    asm volatile("cp.async.commit_group;" ::: "memory");

    if (tid < 32) {
        reinterpret_cast<float4*>(smem + SBIAS)[tid] =
            reinterpret_cast<const float4*>(bias)[tid];
    }
    // token index cache: halo rows p=0..259 -> seq s0+p-2 (or -1 if OOB)
    for (int p = tid; p < 260; p += THREADS) {
        int s = s0 + p - 2;
        reinterpret_cast<int*>(smem + SIDX)[p] =
            (s >= 0 && s < CE_S) ? x[batch * CE_S + s] : -1;
    }
    __syncthreads();

    // ---- stage halo'd A once: rows p=0..259, fp16 ----
    #pragma unroll
    for (int it = 0; it < 17; ++it) {
        int idx = tid + it * THREADS;              // 260*16 = 4160 tasks (32B each)
        if (idx < 260 * 16) {
            int p = idx >> 4;
            int c = idx & 15;                      // 16B fp16 granule = 8 elems
            int tok = reinterpret_cast<const int*>(smem + SIDX)[p];
            float4 v0 = make_float4(0.f, 0.f, 0.f, 0.f);
            float4 v1 = v0;
            if (tok >= 0) {
                const float* e = emb + (size_t)tok * 128 + c * 8;
                v0 = *reinterpret_cast<const float4*>(e);
                v1 = *reinterpret_cast<const float4*>(e + 4);
            }
            *reinterpret_cast<uint4*>(smem + SA + p * ROW_B + c * 16) = cvt8_f16(v0, v1);
        }
    }

    float acc[4][8][4];
    #pragma unroll
    for (int i = 0; i < 4; ++i)
        #pragma unroll
        for (int j = 0; j < 8; ++j)
            #pragma unroll
            for (int r = 0; r < 4; ++r)
                acc[i][j][r] = 0.f;

    // per-lane ldmatrix offsets
    const uint32_t a_off = ((lid & 7) + ((lid >> 3) & 1) * 8) * ROW_B + (lid >> 4) * 16;
    // B (x4, j-paired): lanes 0-15 -> n-tile 2jp (k halves), 16-31 -> n-tile 2jp+1
    const uint32_t b_off = ((lid & 7) + (lid >> 4) * 8) * ROW_B + ((lid >> 3) & 1) * 16;

    // ---- 5 chunks of K=128, 3-slot ring, ONE sync per chunk ----
    #pragma unroll
    for (int s = 0; s < 5; ++s) {
        if (s < 4) {
            asm volatile("cp.async.wait_group 1;" ::: "memory");
        } else {
            asm volatile("cp.async.wait_group 0;" ::: "memory");
        }
        __syncthreads();
        if (s < 3) {
            stage_w(sb + SW_BASE + ((s + 2) % 3) * SW_SLOT, s + 2, tid);
            asm volatile("cp.async.commit_group;" ::: "memory");
        }

        const uint32_t swb = sb + SW_BASE + (s % 3) * SW_SLOT;
        const uint32_t aA  = sb + SA + (wm * 64 + s) * ROW_B + a_off;
        const uint32_t aB  = swb + wn * 64 * ROW_B + b_off;

        #pragma unroll
        for (int ks = 0; ks < 8; ++ks) {
            const uint32_t kb = ks * 32;
            uint32_t Ah[4][4], Bp[4][4];
            #pragma unroll
            for (int i = 0; i < 4; ++i)
                ldsm4(Ah[i], aA + i * (16 * ROW_B) + kb);
            #pragma unroll
            for (int jp = 0; jp < 4; ++jp)
                ldsm4(Bp[jp], aB + jp * (16 * ROW_B) + kb);
            #pragma unroll
            for (int i = 0; i < 4; ++i)
                #pragma unroll
                for (int j = 0; j < 8; ++j)
                    mma_f16(acc[i][j], Ah[i], &Bp[j >> 1][(j & 1) * 2]);
        }
    }

    // ---- epilogue: bias + fast GELU + store ----
    const float* bs = reinterpret_cast<const float*>(smem + SBIAS);
    #pragma unroll
    for (int i = 0; i < 4; ++i) {
        int row0 = s0 + wm * 64 + i * 16 + g;
        #pragma unroll
        for (int j = 0; j < 8; ++j) {
            int col = wn * 64 + j * 8 + q * 2;
            float b0 = bs[col], b1 = bs[col + 1];
            float2 v0, v1;
            v0.x = gelu_fast(acc[i][j][0] + b0);
            v0.y = gelu_fast(acc[i][j][1] + b1);
            v1.x = gelu_fast(acc[i][j][2] + b0);
            v1.y = gelu_fast(acc[i][j][3] + b1);
            float* p0 = out + ((size_t)(batch * CE_S + row0)) * 128 + col;
            *reinterpret_cast<float2*>(p0) = v0;
            *reinterpret_cast<float2*>(p0 + 8 * 128) = v1;
        }
    }
}

extern "C" void kernel_launch(void* const* d_in, const int* in_sizes, int n_in,
                              void* d_out, int out_size)
{
    const int*   x    = (const int*)  d_in[0];
    const float* emb  = (const float*)d_in[1];
    const float* W    = (const float*)d_in[2];
    const float* bias = (const float*)d_in[3];
    float*       out  = (float*)d_out;

    prep_w_kernel<<<40, 256>>>(W);

    cudaFuncSetAttribute(conv_encoder_hmma,
                         cudaFuncAttributeMaxDynamicSharedMemorySize, SM_TOT);
    dim3 grid(CE_S / TOK, 16);   // 8 x 16 = 128 CTAs (one wave)
    conv_encoder_hmma<<<grid, THREADS, SM_TOT>>>(x, emb, bias, out);
}